// round 1
// baseline (speedup 1.0000x reference)
#include <cuda_runtime.h>
#include <math.h>

#define CCH   64
#define PIX   262144
#define KINST 16
#define NCLS  11
#define EPSV  1e-8f
#define GRID1 128
#define T1    2048
#define GRID2 128

// ---------------- scratch (device globals; no allocation) ----------------
__device__ float g_partial1[GRID1][1056];   // [k*64+c] pcs, [1024+k] sumsq, [1040+k] counts
__device__ float g_red[1056];
__device__ __align__(16) float g_meansT[CCH][KINST];  // [c][k]
__device__ float g_nm[KINST];
__device__ float g_cntmax[KINST];
__device__ float g_counts_g[KINST];
__device__ float g_std[KINST];
__device__ float g_partial2[GRID2][256];    // v = i*16 + j

// ---------------- Pass 1: masked per-channel sums, sumsq, counts ----------
__global__ __launch_bounds__(512, 1) void k1_pass1(const float* __restrict__ X1,
                                                   const int* __restrict__ masks) {
    __shared__ unsigned pm_sh[T1];
    __shared__ float stage_q[16][16];
    __shared__ float stage_c[16][16];

    int tid = threadIdx.x, w = tid >> 5, lane = tid & 31;
    int cb = w * 4;

    float a0[16], a1[16], a2[16], a3[16], q[16];
#pragma unroll
    for (int k = 0; k < 16; k++) { a0[k] = a1[k] = a2[k] = a3[k] = q[k] = 0.f; }
    int cnt_i = 0;  // lanes<16: popcount of mask bit == lane

    const int ntiles = PIX / T1;  // 128
    for (int t = blockIdx.x; t < ntiles; t += gridDim.x) {
        int base = t * T1;
        // pack masks -> 16-bit patterns; counts via ballot
        for (int lp = tid; lp < T1; lp += 512) {
            int p = base + lp;
            unsigned pm = 0;
#pragma unroll
            for (int k = 0; k < 16; k++)
                pm |= (masks[k * PIX + p] == 1) ? (1u << k) : 0u;
            pm_sh[lp] = pm;
#pragma unroll
            for (int k = 0; k < 16; k++) {
                unsigned bal = __ballot_sync(0xffffffffu, (pm >> k) & 1u);
                if (lane == k) cnt_i += __popc(bal);
            }
        }
        __syncthreads();

        const float* p0 = X1 + (size_t)(cb + 0) * PIX + base;
        const float* p1 = X1 + (size_t)(cb + 1) * PIX + base;
        const float* p2 = X1 + (size_t)(cb + 2) * PIX + base;
        const float* p3 = X1 + (size_t)(cb + 3) * PIX + base;

        for (int lp = lane; lp < T1; lp += 32) {
            unsigned pm = pm_sh[lp];
            float x0 = p0[lp], x1 = p1[lp], x2 = p2[lp], x3 = p3[lp];
            float s2 = fmaf(x0, x0, fmaf(x1, x1, fmaf(x2, x2, x3 * x3)));
#pragma unroll
            for (int k = 0; k < 16; k++) {
                if (pm & (1u << k)) {
                    a0[k] += x0; a1[k] += x1; a2[k] += x2; a3[k] += x3;
                    q[k] += s2;
                }
            }
        }
        __syncthreads();
    }

    // warp butterfly reduce
#pragma unroll
    for (int k = 0; k < 16; k++) {
#pragma unroll
        for (int s = 16; s > 0; s >>= 1) {
            a0[k] += __shfl_xor_sync(0xffffffffu, a0[k], s);
            a1[k] += __shfl_xor_sync(0xffffffffu, a1[k], s);
            a2[k] += __shfl_xor_sync(0xffffffffu, a2[k], s);
            a3[k] += __shfl_xor_sync(0xffffffffu, a3[k], s);
            q[k]  += __shfl_xor_sync(0xffffffffu, q[k],  s);
        }
    }

    if (lane == 0) {
#pragma unroll
        for (int k = 0; k < 16; k++) {
            g_partial1[blockIdx.x][k * 64 + cb + 0] = a0[k];
            g_partial1[blockIdx.x][k * 64 + cb + 1] = a1[k];
            g_partial1[blockIdx.x][k * 64 + cb + 2] = a2[k];
            g_partial1[blockIdx.x][k * 64 + cb + 3] = a3[k];
            stage_q[w][k] = q[k];
        }
    }
    if (lane < 16) stage_c[w][lane] = (float)cnt_i;
    __syncthreads();
    if (tid < 16) {
        float sq = 0.f, sc = 0.f;
#pragma unroll
        for (int w2 = 0; w2 < 16; w2++) { sq += stage_q[w2][tid]; sc += stage_c[w2][tid]; }
        g_partial1[blockIdx.x][1024 + tid] = sq;
        g_partial1[blockIdx.x][1040 + tid] = sc;
    }
}

// ---------------- deterministic cross-block reduce --------------------
__global__ void k2_reduce1() {
    int v = blockIdx.x * blockDim.x + threadIdx.x;
    if (v < 1056) {
        float s = 0.f;
        for (int b = 0; b < GRID1; b++) s += g_partial1[b][v];
        g_red[v] = s;
    }
}

// ---------------- per-instance stats (means, norm, std) ----------------
__global__ void k3_stats() {
    int k = threadIdx.x;
    if (k < 16) {
        float counts = g_red[1040 + k];
        float cnt = fmaxf(counts, 1.f);
        float sumsq = g_red[1024 + k];
        float sa = 0.f, nm2 = 0.f;
        for (int c = 0; c < CCH; c++) {
            float pcs = g_red[k * 64 + c];
            sa += pcs;
            float m = pcs / cnt;
            g_meansT[c][k] = m;
            nm2 += m * m;
        }
        g_nm[k] = sqrtf(nm2);
        g_cntmax[k] = cnt;
        g_counts_g[k] = counts;
        float ne = counts * (float)CCH;
        float ma = sa / fmaxf(ne, 1.f);
        float var = (sumsq - ne * ma * ma) / fmaxf(ne - 1.f, 1.f);
        g_std[k] = sqrtf(fmaxf(var, 0.f));
    }
}

// ---------------- Pass 2: sim numerators ----------------
__global__ __launch_bounds__(512, 1) void k4_pass2(const float* __restrict__ X2,
                                                   const int* __restrict__ masks) {
    __shared__ __align__(16) float means_sh[CCH][16];
    __shared__ float nm_sh[16];
    __shared__ __align__(16) float buf[16][512];  // ratio buffer / staging overlay

    int tid = threadIdx.x, w = tid >> 5, lane = tid & 31;
    for (int i = tid; i < CCH * 16; i += 512)
        ((float*)means_sh)[i] = ((const float*)g_meansT)[i];
    if (tid < 16) nm_sh[tid] = g_nm[tid];
    __syncthreads();

    float nm_local[16];
#pragma unroll
    for (int i = 0; i < 16; i++) nm_local[i] = nm_sh[i];

    float acc[8];
#pragma unroll
    for (int j = 0; j < 8; j++) acc[j] = 0.f;
    int myi = lane & 15, sh = (lane >> 4) * 8;

    const int NB = PIX / 32;  // 8192 pixel batches
    for (int bt = blockIdx.x * 16 + w; bt < NB; bt += gridDim.x * 16) {
        int p = bt * 32 + lane;
        unsigned pm = 0;
#pragma unroll
        for (int k = 0; k < 16; k++)
            pm |= (masks[k * PIX + p] == 1) ? (1u << k) : 0u;

        float d[16];
#pragma unroll
        for (int i = 0; i < 16; i++) d[i] = 0.f;
        float n2 = 0.f;
#pragma unroll 16
        for (int c = 0; c < CCH; c++) {
            float x = X2[(size_t)c * PIX + p];
            n2 = fmaf(x, x, n2);
            float4 m0 = *(const float4*)&means_sh[c][0];
            float4 m1 = *(const float4*)&means_sh[c][4];
            float4 m2 = *(const float4*)&means_sh[c][8];
            float4 m3 = *(const float4*)&means_sh[c][12];
            d[0]  = fmaf(x, m0.x, d[0]);  d[1]  = fmaf(x, m0.y, d[1]);
            d[2]  = fmaf(x, m0.z, d[2]);  d[3]  = fmaf(x, m0.w, d[3]);
            d[4]  = fmaf(x, m1.x, d[4]);  d[5]  = fmaf(x, m1.y, d[5]);
            d[6]  = fmaf(x, m1.z, d[6]);  d[7]  = fmaf(x, m1.w, d[7]);
            d[8]  = fmaf(x, m2.x, d[8]);  d[9]  = fmaf(x, m2.y, d[9]);
            d[10] = fmaf(x, m2.z, d[10]); d[11] = fmaf(x, m2.w, d[11]);
            d[12] = fmaf(x, m3.x, d[12]); d[13] = fmaf(x, m3.y, d[13]);
            d[14] = fmaf(x, m3.z, d[14]); d[15] = fmaf(x, m3.w, d[15]);
        }
        float n2s = sqrtf(n2);
#pragma unroll
        for (int i = 0; i < 16; i += 4) {
            float4 r;
            r.x = __fdividef(d[i + 0], fmaxf(nm_local[i + 0] * n2s, EPSV));
            r.y = __fdividef(d[i + 1], fmaxf(nm_local[i + 1] * n2s, EPSV));
            r.z = __fdividef(d[i + 2], fmaxf(nm_local[i + 2] * n2s, EPSV));
            r.w = __fdividef(d[i + 3], fmaxf(nm_local[i + 3] * n2s, EPSV));
            *(float4*)&buf[w][lane * 16 + i] = r;
        }
        __syncwarp();
#pragma unroll
        for (int px = 0; px < 32; px++) {
            unsigned pmv = __shfl_sync(0xffffffffu, pm, px);
            float rv = buf[w][px * 16 + myi];
            unsigned pb = pmv >> sh;
#pragma unroll
            for (int jj = 0; jj < 8; jj++)
                if (pb & (1u << jj)) acc[jj] += rv;
        }
        __syncwarp();
    }

    // stage per-warp partial sims (overlay buf[w][0..255], ratio is dead)
#pragma unroll
    for (int jj = 0; jj < 8; jj++)
        buf[w][myi * 16 + sh + jj] = acc[jj];
    __syncthreads();
    for (int v = tid; v < 256; v += 512) {
        float s = 0.f;
#pragma unroll
        for (int w2 = 0; w2 < 16; w2++) s += buf[w2][v];
        g_partial2[blockIdx.x][v] = s;
    }
}

// ---------------- final reduce + class/bucket logic ----------------
__device__ __forceinline__ bool gpred(int b, int l) {
    if (b == 0) return (l >= 1) && (l <= 8);
    if (b == 1) return (l >= 3) && (l <= 10);
    return ((l >= 1) && (l <= 2)) || ((l >= 9) && (l <= 10));
}

__global__ void k5_final(const int* __restrict__ labels, float* __restrict__ out) {
    __shared__ float sim[256];
    __shared__ int lab_sh[16];
    __shared__ float std_sh[16];
    int tid = threadIdx.x;
    if (tid < 256) {
        float s = 0.f;
        for (int b = 0; b < GRID2; b++) s += g_partial2[b][tid];
        sim[tid] = s / g_cntmax[tid & 15];  // v = i*16 + j, divide by cnt[j]
    }
    if (tid < 16) { lab_sh[tid] = labels[tid]; std_sh[tid] = g_std[tid]; }
    __syncthreads();

    if (tid < NCLS) {
        int cl = tid;
        float cc = 0.f, inst = 0.f, cstd = 0.f, csim = 0.f;
        for (int k = 0; k < 16; k++) {
            if (lab_sh[k] == cl) {
                cc += 1.f;
                inst += sim[k * 16 + k];
                cstd += std_sh[k];
            }
        }
        for (int i = 0; i < 16; i++) {
            if (lab_sh[i] != cl) continue;
            for (int j = 0; j < 16; j++)
                if (j != i && lab_sh[j] == cl) csim += sim[i * 16 + j];
        }
        bool many = cc > 1.f;
        out[cl]       = many ? inst / fmaxf(cc, 1.f) : inst;
        out[11 + cl]  = many ? csim / fmaxf(cc * (cc - 1.f), 1.f) : csim;
        out[25 + cl]  = many ? cstd / fmaxf(cc, 1.f) : cstd;
    }
    if (tid >= 32 && tid < 35) {
        int b = tid - 32;
        float s = 0.f;
        int c = 0;
        for (int i = 0; i < 16; i++) {
            if (!gpred(b, lab_sh[i])) continue;
            for (int j = 0; j < 16; j++) {
                if (lab_sh[j] != lab_sh[i] && gpred(b, lab_sh[j])) {
                    c++;
                    s += sim[i * 16 + j];
                }
            }
        }
        out[22 + b] = (c > 1) ? s / (float)c : s;
    }
}

// ---------------- launcher ----------------
extern "C" void kernel_launch(void* const* d_in, const int* in_sizes, int n_in,
                              void* d_out, int out_size) {
    const float* v1     = (const float*)d_in[0];
    const float* v2     = (const float*)d_in[1];
    const int*   masks  = (const int*)d_in[2];
    const int*   labels = (const int*)d_in[3];
    float* out = (float*)d_out;

    k1_pass1<<<GRID1, 512>>>(v1, masks);
    k2_reduce1<<<9, 128>>>();
    k3_stats<<<1, 32>>>();
    k4_pass2<<<GRID2, 512>>>(v2, masks);
    k5_final<<<1, 256>>>(labels, out);
}